// round 7
// baseline (speedup 1.0000x reference)
#include <cuda_runtime.h>
#include <cstdint>

#define NN   100000
#define EE   1600000
#define BB   512
#define EPN  200000
#define HID  72
#define EPSBN 1e-5f

// ---------------- scratch (device globals) ----------------
__device__ __align__(16) float    g_deg[NN];
__device__ __align__(16) float    g_norm[EE];
__device__ __align__(16) float    g_h[NN * HID];
__device__ __align__(16) float    g_t[NN * HID];
__device__ __align__(16) float    g_acc[NN * HID];
__device__ __align__(16) float    g_e[NN * HID];
__device__ __align__(16) float    g_sum[HID];
__device__ __align__(16) float    g_sq[HID];
__device__ __align__(16) float    g_scale[HID];
__device__ __align__(16) float    g_shift[HID];
__device__ __align__(16) float    g_p1[BB * 2 * HID];
__device__ __align__(16) unsigned g_p2[BB * 2 * HID];
__device__ __align__(16) float    g_cnt[BB];
__device__ __align__(16) float    g_Ya[BB * HID];
__device__ __align__(16) float    g_Yb[BB * HID];

__device__ __forceinline__ unsigned fenc(float f) {
    unsigned u = __float_as_uint(f);
    return (u & 0x80000000u) ? ~u : (u | 0x80000000u);
}
__device__ __forceinline__ float fdec(unsigned u) {
    return (u & 0x80000000u) ? __uint_as_float(u ^ 0x80000000u) : __uint_as_float(~u);
}
#define ENC_NEG_INF 0x007FFFFFu

// ---------------- resets ----------------
__global__ void reset_deg() {
    int i = blockIdx.x * blockDim.x + threadIdx.x;
    if (i < NN) g_deg[i] = 0.f;
}
__global__ void reset_bnstats() {
    int i = threadIdx.x;
    if (i < HID) { g_sum[i] = 0.f; g_sq[i] = 0.f; }
}
__global__ void reset_pool() {
    int i = blockIdx.x * blockDim.x + threadIdx.x;
    if (i < BB * 2 * HID) { g_p1[i] = 0.f; g_p2[i] = ENC_NEG_INF; }
    if (i < BB) g_cnt[i] = 0.f;
}

// ---------------- degree / norm ----------------
__global__ void degree_kernel(const int* __restrict__ eidx) {
    int i = blockIdx.x * blockDim.x + threadIdx.x;
    if (i < EE) atomicAdd(&g_deg[eidx[EE + i]], 1.0f);
}
__global__ void norm_kernel(const int* __restrict__ eidx) {
    int i = blockIdx.x * blockDim.x + threadIdx.x;
    if (i >= EE) return;
    float dr = g_deg[eidx[i]];
    float dc = g_deg[eidx[EE + i]];
    float a = dr > 0.f ? rsqrtf(dr) : 0.f;
    float b = dc > 0.f ? rsqrtf(dc) : 0.f;
    g_norm[i] = a * b;
}

// ---------------- register-tiled GEMM ----------------
// MODE 0: g_h = relu(x @ W1 + bias)        (K=64)
// MODE 1: g_e = relu(emb @ W1 + bias)      (K=64)
// MODE 2: g_t = h @ W1 ; g_acc = h @ W2 + bias        (K=72)
// MODE 3: same as 2 but h gets prev-layer BN applied on load
// Block: BM=64 rows, 288 threads = 32 rowgroups(TM=2) x 9 colgroups(TN=8).
template <int K, int MODE>
__global__ __launch_bounds__(288) void gemm_tiled(const float* __restrict__ in,
                                                  const float* __restrict__ W1,
                                                  const float* __restrict__ W2,
                                                  const float* __restrict__ bias) {
    const int BM = 64, INP = K + 4, WP = 76;
    __shared__ float s_in[BM * INP];
    __shared__ float s_w[72 * WP];
    const int tid = threadIdx.x;
    const int colg = tid % 9, rowg = tid / 9;
    const int row0 = blockIdx.x * BM;
    const float* __restrict__ src = (MODE >= 2) ? g_h : in;

    // stage input tile (vectorized, coalesced), optional BN on load
    for (int i = tid; i < BM * K / 4; i += 288) {
        int r = (i * 4) / K, c = (i * 4) % K;
        float4 v = make_float4(0.f, 0.f, 0.f, 0.f);
        if (row0 + r < NN) v = *(const float4*)&src[(size_t)(row0 + r) * K + c];
        if (MODE == 3) {
            float4 sc = *(const float4*)&g_scale[c];
            float4 sh = *(const float4*)&g_shift[c];
            v.x = v.x * sc.x + sh.x; v.y = v.y * sc.y + sh.y;
            v.z = v.z * sc.z + sh.z; v.w = v.w * sc.w + sh.w;
        }
        *(float4*)&s_in[r * INP + c] = v;
    }
    // stage W1
    for (int i = tid; i < K * 72 / 4; i += 288) {
        int r = (i * 4) / 72, c = (i * 4) % 72;
        *(float4*)&s_w[r * WP + c] = *(const float4*)&W1[i * 4];
    }
    __syncthreads();

    float acc[2][8];
#pragma unroll
    for (int i = 0; i < 2; i++)
#pragma unroll
        for (int j = 0; j < 8; j++) acc[i][j] = 0.f;

#pragma unroll 6
    for (int k = 0; k < K; k += 4) {
        float4 a0 = *(const float4*)&s_in[(rowg * 2 + 0) * INP + k];
        float4 a1 = *(const float4*)&s_in[(rowg * 2 + 1) * INP + k];
        float a0a[4] = {a0.x, a0.y, a0.z, a0.w};
        float a1a[4] = {a1.x, a1.y, a1.z, a1.w};
#pragma unroll
        for (int kk = 0; kk < 4; kk++) {
            float4 w0 = *(const float4*)&s_w[(k + kk) * WP + colg * 8];
            float4 w1 = *(const float4*)&s_w[(k + kk) * WP + colg * 8 + 4];
            float wv[8] = {w0.x, w0.y, w0.z, w0.w, w1.x, w1.y, w1.z, w1.w};
#pragma unroll
            for (int j = 0; j < 8; j++) {
                acc[0][j] += a0a[kk] * wv[j];
                acc[1][j] += a1a[kk] * wv[j];
            }
        }
    }

    if (MODE <= 1) {
        float* __restrict__ out = (MODE == 0) ? g_h : g_e;
#pragma unroll
        for (int i = 0; i < 2; i++) {
            int r = row0 + rowg * 2 + i;
            if (r < NN) {
#pragma unroll
                for (int j = 0; j < 8; j += 4) {
                    int c = colg * 8 + j;
                    *(float4*)&out[r * 72 + c] = make_float4(
                        fmaxf(acc[i][j + 0] + bias[c + 0], 0.f),
                        fmaxf(acc[i][j + 1] + bias[c + 1], 0.f),
                        fmaxf(acc[i][j + 2] + bias[c + 2], 0.f),
                        fmaxf(acc[i][j + 3] + bias[c + 3], 0.f));
                }
            }
        }
    } else {
        // first GEMM -> g_t (no bias)
#pragma unroll
        for (int i = 0; i < 2; i++) {
            int r = row0 + rowg * 2 + i;
            if (r < NN) {
#pragma unroll
                for (int j = 0; j < 8; j += 4) {
                    int c = colg * 8 + j;
                    *(float4*)&g_t[r * 72 + c] = make_float4(acc[i][j], acc[i][j + 1],
                                                             acc[i][j + 2], acc[i][j + 3]);
                }
            }
        }
        __syncthreads();
        // stage W2, second GEMM -> g_acc (+bias)
        for (int i = tid; i < K * 72 / 4; i += 288) {
            int r = (i * 4) / 72, c = (i * 4) % 72;
            *(float4*)&s_w[r * WP + c] = *(const float4*)&W2[i * 4];
        }
        __syncthreads();
#pragma unroll
        for (int i = 0; i < 2; i++)
#pragma unroll
            for (int j = 0; j < 8; j++) acc[i][j] = bias[colg * 8 + j];
#pragma unroll 6
        for (int k = 0; k < K; k += 4) {
            float4 a0 = *(const float4*)&s_in[(rowg * 2 + 0) * INP + k];
            float4 a1 = *(const float4*)&s_in[(rowg * 2 + 1) * INP + k];
            float a0a[4] = {a0.x, a0.y, a0.z, a0.w};
            float a1a[4] = {a1.x, a1.y, a1.z, a1.w};
#pragma unroll
            for (int kk = 0; kk < 4; kk++) {
                float4 w0 = *(const float4*)&s_w[(k + kk) * WP + colg * 8];
                float4 w1 = *(const float4*)&s_w[(k + kk) * WP + colg * 8 + 4];
                float wv[8] = {w0.x, w0.y, w0.z, w0.w, w1.x, w1.y, w1.z, w1.w};
#pragma unroll
                for (int j = 0; j < 8; j++) {
                    acc[0][j] += a0a[kk] * wv[j];
                    acc[1][j] += a1a[kk] * wv[j];
                }
            }
        }
#pragma unroll
        for (int i = 0; i < 2; i++) {
            int r = row0 + rowg * 2 + i;
            if (r < NN) {
#pragma unroll
                for (int j = 0; j < 8; j += 4) {
                    int c = colg * 8 + j;
                    *(float4*)&g_acc[r * 72 + c] = make_float4(acc[i][j], acc[i][j + 1],
                                                               acc[i][j + 2], acc[i][j + 3]);
                }
            }
        }
    }
}

// ---------------- edge scatter: acc[col] += norm * t[row] ----------------
// 256 edges/block; indices+norm in regs; 18 x vec4 RED per edge
__global__ __launch_bounds__(256) void scatter_edges(const int* __restrict__ eidx) {
    int e = blockIdx.x * 256 + threadIdx.x;   // EE = 6250 * 256 exact
    int r = eidx[e] * HID;
    int c = eidx[EE + e] * HID;
    float nrm = g_norm[e];
#pragma unroll
    for (int i = 0; i < 18; i++) {
        float4 v = *(const float4*)(g_t + r + i * 4);
        asm volatile("red.global.add.v4.f32 [%0], {%1,%2,%3,%4};"
                     :: "l"(g_acc + c + i * 4), "f"(v.x * nrm), "f"(v.y * nrm),
                        "f"(v.z * nrm), "f"(v.w * nrm)
                     : "memory");
    }
}

// ---------------- batchnorm stats: h <- relu(acc); per-channel sum/sq ----------------
__global__ __launch_bounds__(288) void bn_stats() {
    int tid = threadIdx.x;
    int c = tid % HID, rg = tid / HID;   // 4 row lanes
    float lsum = 0.f, lsq = 0.f;
    for (int r = blockIdx.x * 4 + rg; r < NN; r += gridDim.x * 4) {
        float v = fmaxf(g_acc[r * HID + c], 0.f);
        g_h[r * HID + c] = v;
        lsum += v; lsq += v * v;
    }
    __shared__ float ssum[288], ssq[288];
    ssum[tid] = lsum; ssq[tid] = lsq;
    __syncthreads();
    if (tid < HID) {
        float s = ssum[tid] + ssum[tid + 72] + ssum[tid + 144] + ssum[tid + 216];
        float q = ssq[tid] + ssq[tid + 72] + ssq[tid + 144] + ssq[tid + 216];
        atomicAdd(&g_sum[tid], s);
        atomicAdd(&g_sq[tid], q);
    }
}
__global__ void bn_finalize(const float* __restrict__ gamma, const float* __restrict__ beta) {
    int c = threadIdx.x;
    if (c >= HID) return;
    float mu = g_sum[c] * (1.0f / NN);
    float var = g_sq[c] * (1.0f / NN) - mu * mu;
    float inv = rsqrtf(var + EPSBN);
    float sc = inv * gamma[c];
    g_scale[c] = sc;
    g_shift[c] = beta[c] - mu * sc;
}

// ---------------- pooling (layer-3 BN fused into h read) ----------------
__global__ void pool_kernel(const float* __restrict__ assign) {
    int w = (blockIdx.x * blockDim.x + threadIdx.x) >> 5;
    int lane = threadIdx.x & 31;
    if (w >= NN) return;
    const float* a = assign + (size_t)w * BB;
    float best = -__int_as_float(0x7f800000);
    int bi = 0x7fffffff;
    for (int j = lane; j < BB; j += 32) {
        float v = a[j];
        if (v > best) { best = v; bi = j; }
    }
#pragma unroll
    for (int off = 16; off; off >>= 1) {
        float ov = __shfl_xor_sync(0xffffffffu, best, off);
        int oi = __shfl_xor_sync(0xffffffffu, bi, off);
        if (ov > best || (ov == best && oi < bi)) { best = ov; bi = oi; }
    }
    int b = bi;
    for (int c = lane; c < 2 * HID; c += 32) {
        float zv;
        if (c < HID) zv = g_h[w * HID + c] * g_scale[c] + g_shift[c];
        else         zv = g_e[w * HID + (c - HID)];
        atomicAdd(&g_p1[b * (2 * HID) + c], zv);
        atomicMax(&g_p2[b * (2 * HID) + c], fenc(zv));
    }
    if (lane == 0) atomicAdd(&g_cnt[b], 1.0f);
}

// ---------------- xp build + factored pair-MLP first layer ----------------
__global__ void xp_kernel(const float* __restrict__ w1, const float* __restrict__ b1) {
    __shared__ float s_xp[6 * HID];
    int b = blockIdx.x;
    int t = threadIdx.x;  // 144
    float cnt = g_cnt[b];
    float p1v = g_p1[b * 144 + t];
    s_xp[t] = p1v;
    s_xp[144 + t] = fdec(g_p2[b * 144 + t]);
    s_xp[288 + t] = p1v / fmaxf(cnt, 1.0f);
    __syncthreads();
    int j = (t < HID) ? t : t - HID;
    const float* w = (t < HID) ? w1 : (w1 + 6 * HID * HID);
    float acc = (t < HID) ? b1[j] : 0.f;
    for (int k = 0; k < 6 * HID; k++) acc += s_xp[k] * w[k * HID + j];
    if (t < HID) g_Ya[b * HID + j] = acc;
    else         g_Yb[b * HID + j] = acc;
}

// ---------------- pair output ----------------
__global__ void pair_kernel(const int* __restrict__ pe, const float* __restrict__ w2,
                            const float* __restrict__ b2, float* __restrict__ out) {
    int w = (blockIdx.x * blockDim.x + threadIdx.x) >> 5;
    int lane = threadIdx.x & 31;
    if (w >= EPN) return;
    int a = pe[w];
    int b = pe[EPN + w];
    float acc = 0.f;
    for (int c = lane; c < HID; c += 32) {
        float v = g_Ya[a * HID + c] + g_Yb[b * HID + c];
        acc += tanhf(v) * w2[c];
    }
#pragma unroll
    for (int off = 16; off; off >>= 1) acc += __shfl_xor_sync(0xffffffffu, acc, off);
    if (lane == 0) out[w] = acc + b2[0];
}

// ---------------- launch ----------------
extern "C" void kernel_launch(void* const* d_in, const int* in_sizes, int n_in,
                              void* d_out, int out_size) {
    const float* x         = (const float*)d_in[0];
    const float* emb       = (const float*)d_in[1];
    const float* assign    = (const float*)d_in[2];
    const int*   eidx      = (const int*)d_in[3];
    const int*   pedge     = (const int*)d_in[4];
    const float* node_w    = (const float*)d_in[5];
    const float* node_b    = (const float*)d_in[6];
    const float* emb_w     = (const float*)d_in[7];
    const float* emb_b     = (const float*)d_in[8];
    const float* conv_wi   = (const float*)d_in[9];
    const float* conv_wr   = (const float*)d_in[10];
    const float* conv_bias = (const float*)d_in[11];
    const float* bn_gamma  = (const float*)d_in[12];
    const float* bn_beta   = (const float*)d_in[13];
    const float* mlp_w1    = (const float*)d_in[14];
    const float* mlp_b1    = (const float*)d_in[15];
    const float* mlp_w2    = (const float*)d_in[16];
    const float* mlp_b2    = (const float*)d_in[17];
    float*       out       = (float*)d_out;

    const int GB = (NN + 63) / 64;   // 1563

    reset_deg<<<(NN + 255) / 256, 256>>>();
    degree_kernel<<<EE / 256, 256>>>(eidx);
    norm_kernel<<<EE / 256, 256>>>(eidx);

    gemm_tiled<64, 0><<<GB, 288>>>(x, node_w, nullptr, node_b);
    gemm_tiled<64, 1><<<GB, 288>>>(emb, emb_w, nullptr, emb_b);

    for (int l = 0; l < 3; l++) {
        if (l == 0)
            gemm_tiled<72, 2><<<GB, 288>>>(nullptr, conv_wi + l * HID * HID,
                                           conv_wr + l * HID * HID, conv_bias + l * HID);
        else
            gemm_tiled<72, 3><<<GB, 288>>>(nullptr, conv_wi + l * HID * HID,
                                           conv_wr + l * HID * HID, conv_bias + l * HID);
        scatter_edges<<<EE / 256, 256>>>(eidx);
        reset_bnstats<<<1, 128>>>();
        bn_stats<<<1024, 288>>>();
        bn_finalize<<<1, 128>>>(bn_gamma + l * HID, bn_beta + l * HID);
    }

    reset_pool<<<(BB * 2 * HID + 255) / 256, 256>>>();
    pool_kernel<<<(NN * 32 + 255) / 256, 256>>>(assign);

    xp_kernel<<<BB, 144>>>(mlp_w1, mlp_b1);
    pair_kernel<<<(EPN * 32 + 255) / 256, 256>>>(pedge, mlp_w2, mlp_b2, out);
}

// round 8
// speedup vs baseline: 1.5872x; 1.5872x over previous
#include <cuda_runtime.h>
#include <cstdint>

#define NN   100000
#define EE   1600000
#define BB   512
#define EPN  200000
#define NINK 64
#define HID  72
#define EPSBN 1e-5f
#define SCAN_BLKS ((NN + 1023) / 1024)   // 98

// ---------------- scratch (device globals) ----------------
__device__ __align__(16) int      g_degi[NN];
__device__ __align__(16) int      g_cur[NN];
__device__ __align__(16) int      g_offi[NN];      // inclusive block-scan
__device__ __align__(16) int      g_offx[NN + 1];  // exclusive CSR offsets
__device__ __align__(16) int      g_bsum[SCAN_BLKS + 1];
__device__ __align__(16) float    g_norm[EE];
__device__ __align__(16) int2     g_csr[EE];       // (src row, norm bits) per dest-sorted edge
__device__ __align__(16) float    g_h[NN * HID];
__device__ __align__(16) float    g_t[NN * HID];
__device__ __align__(16) float    g_acc[NN * HID];
__device__ __align__(16) float    g_e[NN * HID];
__device__ __align__(16) float    g_sum[HID];
__device__ __align__(16) float    g_sq[HID];
__device__ __align__(16) float    g_scale[HID];
__device__ __align__(16) float    g_shift[HID];
__device__ __align__(16) float    g_p1[BB * 2 * HID];
__device__ __align__(16) unsigned g_p2[BB * 2 * HID];
__device__ __align__(16) float    g_cnt[BB];
__device__ __align__(16) float    g_Ya[BB * HID];
__device__ __align__(16) float    g_Yb[BB * HID];

__device__ __forceinline__ unsigned fenc(float f) {
    unsigned u = __float_as_uint(f);
    return (u & 0x80000000u) ? ~u : (u | 0x80000000u);
}
__device__ __forceinline__ float fdec(unsigned u) {
    return (u & 0x80000000u) ? __uint_as_float(u ^ 0x80000000u) : __uint_as_float(~u);
}
#define ENC_NEG_INF 0x007FFFFFu

// ---------------- resets ----------------
__global__ void reset_graph() {
    int i = blockIdx.x * blockDim.x + threadIdx.x;
    if (i < NN) { g_degi[i] = 0; g_cur[i] = 0; }
}
__global__ void reset_bnstats() {
    int i = threadIdx.x;
    if (i < HID) { g_sum[i] = 0.f; g_sq[i] = 0.f; }
}
__global__ void reset_pool() {
    int i = blockIdx.x * blockDim.x + threadIdx.x;
    if (i < BB * 2 * HID) { g_p1[i] = 0.f; g_p2[i] = ENC_NEG_INF; }
    if (i < BB) g_cnt[i] = 0.f;
}

// ---------------- degree / norm (int degree) ----------------
__global__ void degree_kernel(const int* __restrict__ eidx) {
    int i = blockIdx.x * blockDim.x + threadIdx.x;
    if (i < EE) atomicAdd(&g_degi[eidx[EE + i]], 1);
}
__global__ void norm_kernel(const int* __restrict__ eidx) {
    int i = blockIdx.x * blockDim.x + threadIdx.x;
    if (i >= EE) return;
    int dr = g_degi[eidx[i]];
    int dc = g_degi[eidx[EE + i]];
    float a = dr > 0 ? rsqrtf((float)dr) : 0.f;
    float b = dc > 0 ? rsqrtf((float)dc) : 0.f;
    g_norm[i] = a * b;
}

// ---------------- CSR build: block scan -> bsum scan -> fix -> fill ----------------
__global__ void scan_block() {
    __shared__ int s[1024];
    int i = blockIdx.x * 1024 + threadIdx.x;
    int v = (i < NN) ? g_degi[i] : 0;
    s[threadIdx.x] = v;
    __syncthreads();
#pragma unroll
    for (int off = 1; off < 1024; off <<= 1) {
        int x = (threadIdx.x >= off) ? s[threadIdx.x - off] : 0;
        __syncthreads();
        s[threadIdx.x] += x;
        __syncthreads();
    }
    if (i < NN) g_offi[i] = s[threadIdx.x];
    if (threadIdx.x == 1023) g_bsum[blockIdx.x] = s[1023];
}
__global__ void scan_bsum() {
    if (threadIdx.x == 0) {
        int run = 0;
        for (int b = 0; b < SCAN_BLKS; b++) { int v = g_bsum[b]; g_bsum[b] = run; run += v; }
        g_offx[NN] = EE;
    }
}
__global__ void scan_fix() {
    int i = blockIdx.x * blockDim.x + threadIdx.x;
    if (i < NN) g_offx[i] = g_offi[i] - g_degi[i] + g_bsum[i >> 10];
}
__global__ void csr_fill(const int* __restrict__ eidx) {
    int e = blockIdx.x * 256 + threadIdx.x;   // EE multiple of 256
    int row = eidx[e], col = eidx[EE + e];
    int pos = g_offx[col] + atomicAdd(&g_cur[col], 1);
    g_csr[pos] = make_int2(row, __float_as_int(g_norm[e]));
}

// ---------------- input GEMM (R4-measured variant): dst = relu(in @ W + b) ----------
template <int K, int DST>
__global__ void gemm_in_relu(const float* __restrict__ in, const float* __restrict__ W,
                             const float* __restrict__ bias) {
    float* __restrict__ out = (DST == 0) ? g_h : g_e;
    const int ROWS = 64;
    __shared__ float s_in[ROWS * (K + 1)];
    __shared__ float s_w[K * HID];
    int row0 = blockIdx.x * ROWS;
    for (int idx = threadIdx.x; idx < ROWS * K; idx += 64) {
        int g = row0 * K + idx;
        float v = (g < NN * K) ? in[g] : 0.f;
        s_in[(idx / K) * (K + 1) + (idx % K)] = v;
    }
    for (int idx = threadIdx.x; idx < K * HID; idx += 64) s_w[idx] = W[idx];
    __syncthreads();
    float acc[HID];
#pragma unroll
    for (int j = 0; j < HID; j++) acc[j] = bias[j];
    for (int k = 0; k < K; k++) {
        float a = s_in[threadIdx.x * (K + 1) + k];
#pragma unroll
        for (int j = 0; j < HID; j++) acc[j] += a * s_w[k * HID + j];
    }
    int row = row0 + threadIdx.x;
    if (row < NN) {
        float4* o = reinterpret_cast<float4*>(out + row * HID);
#pragma unroll
        for (int j = 0; j < HID; j += 4)
            o[j / 4] = make_float4(fmaxf(acc[j], 0.f), fmaxf(acc[j + 1], 0.f),
                                   fmaxf(acc[j + 2], 0.f), fmaxf(acc[j + 3], 0.f));
    }
}

// ---------------- conv layer GEMMs (R4 variant): t = h@Wi ; acc = h@Wr + bias --------
template <bool BN>
__global__ void conv_gemm(const float* __restrict__ Wi, const float* __restrict__ Wr,
                          const float* __restrict__ bias) {
    const int ROWS = 64;
    const int K = HID;
    __shared__ float s_in[ROWS * (K + 1)];
    __shared__ float s_w[K * HID];
    int row0 = blockIdx.x * ROWS;
    for (int idx = threadIdx.x; idx < ROWS * K; idx += 64) {
        int g = row0 * K + idx;
        float v = (g < NN * K) ? g_h[g] : 0.f;
        if (BN) { int c = idx % K; v = v * g_scale[c] + g_shift[c]; }
        s_in[(idx / K) * (K + 1) + (idx % K)] = v;
    }
    for (int idx = threadIdx.x; idx < K * HID; idx += 64) s_w[idx] = Wi[idx];
    __syncthreads();
    int row = row0 + threadIdx.x;
    float acc[HID];
#pragma unroll
    for (int j = 0; j < HID; j++) acc[j] = 0.f;
    for (int k = 0; k < K; k++) {
        float a = s_in[threadIdx.x * (K + 1) + k];
#pragma unroll
        for (int j = 0; j < HID; j++) acc[j] += a * s_w[k * HID + j];
    }
    if (row < NN) {
        float4* o = reinterpret_cast<float4*>(g_t + row * HID);
#pragma unroll
        for (int j = 0; j < HID; j += 4)
            o[j / 4] = make_float4(acc[j], acc[j + 1], acc[j + 2], acc[j + 3]);
    }
    __syncthreads();
    for (int idx = threadIdx.x; idx < K * HID; idx += 64) s_w[idx] = Wr[idx];
    __syncthreads();
#pragma unroll
    for (int j = 0; j < HID; j++) acc[j] = bias[j];
    for (int k = 0; k < K; k++) {
        float a = s_in[threadIdx.x * (K + 1) + k];
#pragma unroll
        for (int j = 0; j < HID; j++) acc[j] += a * s_w[k * HID + j];
    }
    if (row < NN) {
        float4* o = reinterpret_cast<float4*>(g_acc + row * HID);
#pragma unroll
        for (int j = 0; j < HID; j += 4)
            o[j / 4] = make_float4(acc[j], acc[j + 1], acc[j + 2], acc[j + 3]);
    }
}

// ---------------- gather: acc[n] += sum_{e in CSR[n]} norm_e * t[src_e]  (NO atomics) --
// 16 nodes/block x 18 threads/node; each thread owns one float4 channel chunk.
__global__ __launch_bounds__(288) void gather_edges() {
    int tid = threadIdx.x;
    int node = blockIdx.x * 16 + tid / 18;
    int ch = (tid % 18) * 4;
    if (node >= NN) return;
    int p = g_offx[node];
    int end = g_offx[node + 1];
    float* ap = g_acc + node * HID + ch;
    float4 acc = *(float4*)ap;
    if (p < end) {
        int2 rc = g_csr[p];
        for (; p < end; p++) {
            int2 nrc = (p + 1 < end) ? g_csr[p + 1] : rc;   // prefetch next record
            float nrm = __int_as_float(rc.y);
            float4 v = *(const float4*)(g_t + rc.x * HID + ch);
            acc.x += nrm * v.x; acc.y += nrm * v.y;
            acc.z += nrm * v.z; acc.w += nrm * v.w;
            rc = nrc;
        }
    }
    *(float4*)ap = acc;
}

// ---------------- batchnorm stats: h <- relu(acc); per-channel sum/sq ----------------
__global__ __launch_bounds__(288) void bn_stats() {
    int tid = threadIdx.x;
    int c = tid % HID, rg = tid / HID;   // 4 row lanes
    float lsum = 0.f, lsq = 0.f;
    for (int r = blockIdx.x * 4 + rg; r < NN; r += gridDim.x * 4) {
        float v = fmaxf(g_acc[r * HID + c], 0.f);
        g_h[r * HID + c] = v;
        lsum += v; lsq += v * v;
    }
    __shared__ float ssum[288], ssq[288];
    ssum[tid] = lsum; ssq[tid] = lsq;
    __syncthreads();
    if (tid < HID) {
        float s = ssum[tid] + ssum[tid + 72] + ssum[tid + 144] + ssum[tid + 216];
        float q = ssq[tid] + ssq[tid + 72] + ssq[tid + 144] + ssq[tid + 216];
        atomicAdd(&g_sum[tid], s);
        atomicAdd(&g_sq[tid], q);
    }
}
__global__ void bn_finalize(const float* __restrict__ gamma, const float* __restrict__ beta) {
    int c = threadIdx.x;
    if (c >= HID) return;
    float mu = g_sum[c] * (1.0f / NN);
    float var = g_sq[c] * (1.0f / NN) - mu * mu;
    float inv = rsqrtf(var + EPSBN);
    float sc = inv * gamma[c];
    g_scale[c] = sc;
    g_shift[c] = beta[c] - mu * sc;
}

// ---------------- pooling (layer-3 BN fused into h read) ----------------
__global__ void pool_kernel(const float* __restrict__ assign) {
    int w = (blockIdx.x * blockDim.x + threadIdx.x) >> 5;
    int lane = threadIdx.x & 31;
    if (w >= NN) return;
    const float* a = assign + (size_t)w * BB;
    float best = -__int_as_float(0x7f800000);
    int bi = 0x7fffffff;
    for (int j = lane; j < BB; j += 32) {
        float v = a[j];
        if (v > best) { best = v; bi = j; }
    }
#pragma unroll
    for (int off = 16; off; off >>= 1) {
        float ov = __shfl_xor_sync(0xffffffffu, best, off);
        int oi = __shfl_xor_sync(0xffffffffu, bi, off);
        if (ov > best || (ov == best && oi < bi)) { best = ov; bi = oi; }
    }
    int b = bi;
    for (int c = lane; c < 2 * HID; c += 32) {
        float zv;
        if (c < HID) zv = g_h[w * HID + c] * g_scale[c] + g_shift[c];
        else         zv = g_e[w * HID + (c - HID)];
        atomicAdd(&g_p1[b * (2 * HID) + c], zv);
        atomicMax(&g_p2[b * (2 * HID) + c], fenc(zv));
    }
    if (lane == 0) atomicAdd(&g_cnt[b], 1.0f);
}

// ---------------- xp build + factored pair-MLP first layer ----------------
__global__ void xp_kernel(const float* __restrict__ w1, const float* __restrict__ b1) {
    __shared__ float s_xp[6 * HID];
    int b = blockIdx.x;
    int t = threadIdx.x;  // 144
    float cnt = g_cnt[b];
    float p1v = g_p1[b * 144 + t];
    s_xp[t] = p1v;
    s_xp[144 + t] = fdec(g_p2[b * 144 + t]);
    s_xp[288 + t] = p1v / fmaxf(cnt, 1.0f);
    __syncthreads();
    int j = (t < HID) ? t : t - HID;
    const float* w = (t < HID) ? w1 : (w1 + 6 * HID * HID);
    float acc = (t < HID) ? b1[j] : 0.f;
    for (int k = 0; k < 6 * HID; k++) acc += s_xp[k] * w[k * HID + j];
    if (t < HID) g_Ya[b * HID + j] = acc;
    else         g_Yb[b * HID + j] = acc;
}

// ---------------- pair output ----------------
__global__ void pair_kernel(const int* __restrict__ pe, const float* __restrict__ w2,
                            const float* __restrict__ b2, float* __restrict__ out) {
    int w = (blockIdx.x * blockDim.x + threadIdx.x) >> 5;
    int lane = threadIdx.x & 31;
    if (w >= EPN) return;
    int a = pe[w];
    int b = pe[EPN + w];
    float acc = 0.f;
    for (int c = lane; c < HID; c += 32) {
        float v = g_Ya[a * HID + c] + g_Yb[b * HID + c];
        acc += tanhf(v) * w2[c];
    }
#pragma unroll
    for (int off = 16; off; off >>= 1) acc += __shfl_xor_sync(0xffffffffu, acc, off);
    if (lane == 0) out[w] = acc + b2[0];
}

// ---------------- launch ----------------
extern "C" void kernel_launch(void* const* d_in, const int* in_sizes, int n_in,
                              void* d_out, int out_size) {
    const float* x         = (const float*)d_in[0];
    const float* emb       = (const float*)d_in[1];
    const float* assign    = (const float*)d_in[2];
    const int*   eidx      = (const int*)d_in[3];
    const int*   pedge     = (const int*)d_in[4];
    const float* node_w    = (const float*)d_in[5];
    const float* node_b    = (const float*)d_in[6];
    const float* emb_w     = (const float*)d_in[7];
    const float* emb_b     = (const float*)d_in[8];
    const float* conv_wi   = (const float*)d_in[9];
    const float* conv_wr   = (const float*)d_in[10];
    const float* conv_bias = (const float*)d_in[11];
    const float* bn_gamma  = (const float*)d_in[12];
    const float* bn_beta   = (const float*)d_in[13];
    const float* mlp_w1    = (const float*)d_in[14];
    const float* mlp_b1    = (const float*)d_in[15];
    const float* mlp_w2    = (const float*)d_in[16];
    const float* mlp_b2    = (const float*)d_in[17];
    float*       out       = (float*)d_out;

    const int GB = (NN + 63) / 64;   // 1563

    // graph prep: degree, norm, CSR
    reset_graph<<<(NN + 255) / 256, 256>>>();
    degree_kernel<<<EE / 256, 256>>>(eidx);
    norm_kernel<<<EE / 256, 256>>>(eidx);
    scan_block<<<SCAN_BLKS, 1024>>>();
    scan_bsum<<<1, 32>>>();
    scan_fix<<<(NN + 255) / 256, 256>>>();
    csr_fill<<<EE / 256, 256>>>(eidx);

    // input GEMMs
    gemm_in_relu<NINK, 0><<<GB, 64>>>(x, node_w, node_b);
    gemm_in_relu<NINK, 1><<<GB, 64>>>(emb, emb_w, emb_b);

    // 3 ARMA conv layers (gather, no atomics)
    for (int l = 0; l < 3; l++) {
        if (l == 0)
            conv_gemm<false><<<GB, 64>>>(conv_wi + l * HID * HID, conv_wr + l * HID * HID,
                                         conv_bias + l * HID);
        else
            conv_gemm<true><<<GB, 64>>>(conv_wi + l * HID * HID, conv_wr + l * HID * HID,
                                        conv_bias + l * HID);
        gather_edges<<<(NN + 15) / 16, 288>>>();
        reset_bnstats<<<1, 128>>>();
        bn_stats<<<1024, 288>>>();
        bn_finalize<<<1, 128>>>(bn_gamma + l * HID, bn_beta + l * HID);
    }

    // pooling (applies layer-3 BN on read)
    reset_pool<<<(BB * 2 * HID + 255) / 256, 256>>>();
    pool_kernel<<<(NN * 32 + 255) / 256, 256>>>(assign);

    // factored pair MLP
    xp_kernel<<<BB, 144>>>(mlp_w1, mlp_b1);
    pair_kernel<<<(EPN * 32 + 255) / 256, 256>>>(pedge, mlp_w2, mlp_b2, out);
}